// round 17
// baseline (speedup 1.0000x reference)
#include <cuda_runtime.h>
#include <cuda_bf16.h>
#include <cstdint>

// Problem constants
#define BB   4
#define CIN  256
#define COUT 256
#define KTOT 2304
#define KC   32
#define NCH  72          // KTOT/KC
#define APITCH 36        // A smem row pitch in floats (144 B)

// ---------------- device scratch (no allocations allowed) ----------------
__device__ float g_wofft[KTOT * 32];          // offset/mask conv weights [k][oc]
__device__ float g_offmask[BB*64*64*28];      // [b,h,w][28]
// Main weights, tf32, packed in exact B-fragment order per chunk:
// chunk layout: f2 index ((nb*4+s)*8+og)*32 + lane, components (b0,b1)
__device__ __align__(16) float g_wbt[NCH * 8192];   // 2.36 MB

// ---------------- PTX helpers (baseline ISA only: sm_80+ features) ----------------
__device__ __forceinline__ uint32_t smem_u32(const void* p) {
    uint32_t a;
    asm("{ .reg .u64 t; cvta.to.shared.u64 t, %1; cvt.u32.u64 %0, t; }" : "=r"(a) : "l"(p));
    return a;
}
__device__ __forceinline__ void cp16(uint32_t s, const void* g) {
    asm volatile("cp.async.cg.shared.global [%0], [%1], 16;" :: "r"(s), "l"(g));
}
#define CP_COMMIT() asm volatile("cp.async.commit_group;" ::: "memory")
#define CP_WAIT1()  asm volatile("cp.async.wait_group 1;" ::: "memory")
#define CP_WAIT0()  asm volatile("cp.async.wait_group 0;" ::: "memory")

__device__ __forceinline__ uint32_t f2tf32(float f) {
    uint32_t u;
    asm("cvt.rna.tf32.f32 %0, %1;" : "=r"(u) : "f"(f));
    return u;
}
__device__ __forceinline__ void mma_tf32(float* d,
                                         uint32_t a0, uint32_t a1, uint32_t a2, uint32_t a3,
                                         uint32_t b0, uint32_t b1) {
    asm volatile("mma.sync.aligned.m16n8k8.row.col.f32.tf32.tf32.f32 "
                 "{%0,%1,%2,%3}, {%4,%5,%6,%7}, {%8,%9}, {%0,%1,%2,%3};"
                 : "+f"(d[0]), "+f"(d[1]), "+f"(d[2]), "+f"(d[3])
                 : "r"(a0), "r"(a1), "r"(a2), "r"(a3), "r"(b0), "r"(b1));
}

// SMEM layout (bytes, dynamic)
#define BCHUNK 32768                            // 256 o x 32 k x 4B tf32 per chunk
#define SM_B     0                              // double buffered: 2 * 32768 = 65536
#define ABUF     (128 * APITCH * 4)             // 18432 B
#define SM_A     65536                          // double buffered: 2 * 18432 -> ends 102400
#define SM_TADDR 102400                         // u32[9*128*2] packed corner offsets (9216 B)
#define SM_TW    111616                         // float4[9*128] bilinear weights (18432 B)
#define SMEM_TOTAL 130048

// ---------------- prep: tf32 convert + fragment-order pack ----------------
__global__ void prep_kernel(const float* __restrict__ w,
                            const float* __restrict__ off_w,
                            const float* __restrict__ mask_w) {
    int idx = blockIdx.x * blockDim.x + threadIdx.x;
    if (idx < COUT * KTOT) {
        int o = idx / KTOT;
        int k = idx - o * KTOT;          // k = c*9 + tap (matches w layout [o][c][3][3])
        uint32_t tf = f2tf32(__ldg(&w[idx]));
        int ch = k >> 5, kk = k & 31;
        int s  = kk >> 3, kw = kk & 7;
        int bsel = kw >> 2, kq = kw & 3;
        int nb = o >> 6, og = (o >> 3) & 7, ol = o & 7;
        int l  = ol * 4 + kq;
        int f2 = ((nb * 4 + s) * 8 + og) * 32 + l;
        g_wbt[(size_t)ch * 8192 + f2 * 2 + bsel] = __uint_as_float(tf);
    }
    if (idx < KTOT * 32) {
        int oc = idx & 31;
        int k  = idx >> 5;
        float v = 0.f;
        if (oc < 18)      v = __ldg(&off_w [(size_t)oc * KTOT + k]);
        else if (oc < 27) v = __ldg(&mask_w[(size_t)(oc - 18) * KTOT + k]);
        g_wofft[idx] = v;
    }
}

// ---------------- kernel 1: offset/mask conv (unchanged, FFMA) ----------------
#define CC1 16
__global__ __launch_bounds__(256, 2)
void k_offmask(const float* __restrict__ x,
               const float* __restrict__ off_b,
               const float* __restrict__ mask_b) {
    __shared__ float xs[CC1][3][66];
    __shared__ float ws[CC1 * 9 * 32];

    int bh = blockIdx.x;
    int b  = bh >> 6;
    int h  = bh & 63;
    int tid = threadIdx.x;
    int pp = tid & 31;
    int og = tid >> 5;

    const float* xb = x + (size_t)b * CIN * 4096;
    float acc[2][4] = {};

    for (int c0 = 0; c0 < CIN; c0 += CC1) {
        for (int e = tid; e < CC1 * 3 * 66; e += 256) {
            int c   = e / 198;
            int r   = e % 198;
            int row = r / 66;
            int col = r % 66;
            int y  = h - 1 + row;
            int xp = col - 1;
            float v = 0.f;
            if ((unsigned)y < 64u && (unsigned)xp < 64u)
                v = xb[(size_t)(c0 + c) * 4096 + y * 64 + xp];
            xs[c][row][col] = v;
        }
        const float* src = g_wofft + (size_t)c0 * 9 * 32;
        for (int e = tid; e < CC1 * 288; e += 256) ws[e] = src[e];
        __syncthreads();

        for (int c = 0; c < CC1; ++c) {
            #pragma unroll
            for (int t = 0; t < 9; ++t) {
                int ky = t / 3, kx = t % 3;
                float xv0 = xs[c][ky][pp + kx];
                float xv1 = xs[c][ky][pp + 32 + kx];
                const float* wr = &ws[(c * 9 + t) * 32 + og * 4];
                #pragma unroll
                for (int j = 0; j < 4; ++j) {
                    float wv = wr[j];
                    acc[0][j] = fmaf(xv0, wv, acc[0][j]);
                    acc[1][j] = fmaf(xv1, wv, acc[1][j]);
                }
            }
        }
        __syncthreads();
    }

    #pragma unroll
    for (int half = 0; half < 2; ++half) {
        int pix = pp + half * 32;
        float* dst = g_offmask + ((size_t)bh * 64 + pix) * 28;
        #pragma unroll
        for (int j = 0; j < 4; ++j) {
            int oc = og * 4 + j;
            if (oc < 18) {
                dst[oc] = acc[half][j] + __ldg(&off_b[oc]);
            } else if (oc < 27) {
                float z = acc[half][j] + __ldg(&mask_b[oc - 18]);
                dst[oc] = 1.f / (1.f + __expf(-z));
            }
        }
    }
}

// ---------------- kernel 2: deformable sample + single-pass TF32 MMA GEMM ----------------
// CTA: 128 px (2 rows) x 256 outs, 512 threads / 16 warps.
// Warp w: mi = w&3 (32-px tile), nb = w>>2 (64-out block).
// A stored (k,k+4)-interleaved so fragment reads are single LDS.64;
// B pre-packed in exact fragment order by prep (LDS.64 per n8-group).
__global__ __launch_bounds__(512, 1)
void k_main(const float* __restrict__ x,
            const float* __restrict__ bias,
            float* __restrict__ out) {
    extern __shared__ __align__(16) unsigned char smem[];
    uint32_t sbase = smem_u32(smem);
    uint32_t* taddr = (uint32_t*)(smem + SM_TADDR);   // [t*128+px]*2 + {0,1}
    float4*   twt   = (float4*)(smem + SM_TW);        // [t*128+px]

    int tid = threadIdx.x;
    int wid = tid >> 5;
    int lane = tid & 31;
    int bh = blockIdx.x;        // 0..127
    int b  = bh >> 5;
    int hp = bh & 31;           // image rows 2hp, 2hp+1

    // ---- precompute per-(px,tap) gather geometry ----
    for (int e = tid; e < 9 * 128; e += 512) {
        int t  = e >> 7;        // 0..8
        int px = e & 127;
        int r  = px >> 6, wi = px & 63;
        int h_img = 2 * hp + r;
        const float* om = g_offmask + (((size_t)(b * 64 + h_img)) * 64 + wi) * 28;
        float dy = om[2 * t], dx = om[2 * t + 1], m = om[18 + t];
        int kyy = t / 3, kxx = t - 3 * kyy;
        float py  = (float)(h_img - 1 + kyy) + dy;
        float pxf = (float)(wi - 1 + kxx) + dx;
        float y0f = floorf(py), x0f = floorf(pxf);
        int iy = (int)y0f, ix = (int)x0f;
        float fy = py - y0f, fx = pxf - x0f;
        bool y0v = (unsigned)iy       < 64u;
        bool y1v = (unsigned)(iy + 1) < 64u;
        bool x0v = (unsigned)ix       < 64u;
        bool x1v = (unsigned)(ix + 1) < 64u;
        int yc0 = min(max(iy, 0), 63),     yc1 = min(max(iy + 1, 0), 63);
        int xc0 = min(max(ix, 0), 63),     xc1 = min(max(ix + 1, 0), 63);
        float wy0 = 1.f - fy, wx0 = 1.f - fx;
        float4 w;
        w.x = (y0v && x0v) ? wy0 * wx0 * m : 0.f;
        w.y = (y0v && x1v) ? wy0 * fx  * m : 0.f;
        w.z = (y1v && x0v) ? fy  * wx0 * m : 0.f;
        w.w = (y1v && x1v) ? fy  * fx  * m : 0.f;
        taddr[e * 2 + 0] = (uint32_t)(yc0 * 64 + xc0) | ((uint32_t)(yc0 * 64 + xc1) << 16);
        taddr[e * 2 + 1] = (uint32_t)(yc1 * 64 + xc0) | ((uint32_t)(yc1 * 64 + xc1) << 16);
        twt[e] = w;
    }
    __syncthreads();

    const float* xb = x + (size_t)b * CIN * 4096;
    int p_img = tid & 127;      // pixel 0..127
    int ksq = tid >> 7;         // 0..3 = q (fragment column within k8)

    float acc[8][2][4];
    #pragma unroll
    for (int g = 0; g < 8; ++g)
        #pragma unroll
        for (int mt = 0; mt < 2; ++mt)
            #pragma unroll
            for (int j = 0; j < 4; ++j) acc[g][mt][j] = 0.f;

    // prologue: stage B chunk 0 into buffer 0 (32 KB)
    {
        const char* src = (const char*)(g_wbt);
        uint32_t dstb = sbase + SM_B;
        #pragma unroll
        for (int i = 0; i < 4; ++i)
            cp16(dstb + (tid + 512 * i) * 16, src + (size_t)(tid + 512 * i) * 16);
    }
    CP_COMMIT();

    for (int ch = 0; ch <= NCH; ++ch) {
        // ---- stage A chunk ch into buffer ch&1: sample, tf32-convert, pair-store ----
        if (ch < NCH) {
            int p = ch & 1;
            int k0 = ch * KC;
            unsigned aoff = SM_A + p * ABUF + ((uint32_t)p_img * APITCH) * 4u;
            #pragma unroll
            for (int s = 0; s < 4; ++s) {
                uint32_t vv[2];
                #pragma unroll
                for (int half = 0; half < 2; ++half) {
                    int k = k0 + s * 8 + ksq + half * 4;
                    unsigned c = (unsigned)k / 9u;
                    int t = k - 9 * (int)c;
                    int te = t * 128 + p_img;
                    uint32_t a01 = taddr[te * 2 + 0];
                    uint32_t a23 = taddr[te * 2 + 1];
                    float4 w = twt[te];
                    const float* xc = xb + ((size_t)c << 12);
                    float v00 = xc[a01 & 0xFFFFu];
                    float v01 = xc[a01 >> 16];
                    float v10 = xc[a23 & 0xFFFFu];
                    float v11 = xc[a23 >> 16];
                    float v = fmaf(w.w, v11, fmaf(w.z, v10, fmaf(w.y, v01, w.x * v00)));
                    vv[half] = f2tf32(v);
                }
                uint2 st; st.x = vv[0]; st.y = vv[1];
                *(uint2*)(smem + aoff + (uint32_t)(s * 8 + ksq * 2) * 4u) = st;
            }
        }

        // ---- compute chunk ch-1 from buffer (ch-1)&1 ----
        if (ch > 0) {
            int cp = (ch - 1) & 1;
            if (ch == NCH) { CP_WAIT0(); } else { CP_WAIT1(); }   // B of chunk ch-1 resident
            __syncthreads();            // A stores of chunk ch-1 visible, B landed for all

            int mi = wid & 3;
            int nb = wid >> 2;
            int px0 = mi * 32;
            unsigned offA = SM_A + cp * ABUF + (uint32_t)px0 * (APITCH * 4);
            unsigned offB = SM_B + cp * BCHUNK + (uint32_t)nb * 8192u;
            int lr = lane >> 2;         // fragment row within 8
            int lc = lane & 3;          // fragment k-col

            #pragma unroll
            for (int s = 0; s < 4; ++s) {
                unsigned acol = (unsigned)(s * 8 + lc * 2) * 4u;
                uint2 aA = *(const uint2*)(smem + offA + (lr     ) * 144 + acol);  // rows px0+lr    : a0,a2 (mt0)
                uint2 aB = *(const uint2*)(smem + offA + (lr +  8) * 144 + acol);  // rows px0+8+lr  : a1,a3 (mt0)
                uint2 aC = *(const uint2*)(smem + offA + (lr + 16) * 144 + acol);  // mt1
                uint2 aD = *(const uint2*)(smem + offA + (lr + 24) * 144 + acol);
                #pragma unroll
                for (int g = 0; g < 8; ++g) {
                    uint2 bv = *(const uint2*)(smem + offB + ((unsigned)((s * 8 + g) * 32 + lane)) * 8u);
                    mma_tf32(acc[g][0], aA.x, aB.x, aA.y, aB.y, bv.x, bv.y);
                    mma_tf32(acc[g][1], aC.x, aD.x, aC.y, aD.y, bv.x, bv.y);
                }
            }
            __syncthreads();            // all warps done reading buffers before reuse
        }

        // ---- queue B for chunk ch+1 (buffer (ch+1)&1 is now free) ----
        if (ch < NCH && ch + 1 < NCH) {
            const char* src = (const char*)(g_wbt) + (size_t)(ch + 1) * BCHUNK;
            uint32_t dstb = sbase + SM_B + ((ch + 1) & 1) * BCHUNK;
            #pragma unroll
            for (int i = 0; i < 4; ++i)
                cp16(dstb + (tid + 512 * i) * 16, src + (size_t)(tid + 512 * i) * 16);
            CP_COMMIT();
        }
    }

    // ---- epilogue: direct stores from fragments (D mapping same as m16n8k16) ----
    {
        int mi = wid & 3;
        int nb = wid >> 2;
        int px0 = mi * 32;
        int re = px0 >> 6;              // image row of this warp's pixels (0 or 1)
        int h_o = 2 * hp + re;
        #pragma unroll
        for (int g = 0; g < 8; ++g) {
            int o0 = nb * 64 + g * 8 + 2 * (lane & 3);
            float b0 = __ldg(&bias[o0]);
            float b1 = __ldg(&bias[o0 + 1]);
            #pragma unroll
            for (int mt = 0; mt < 2; ++mt) {
                int px = px0 + mt * 16 + (lane >> 2);
                int wo = px & 63;
                float* p0 = out + (((size_t)b * COUT + o0) * 64 + h_o) * 64 + wo;
                p0[0]        = acc[g][mt][0] + b0;
                p0[4096]     = acc[g][mt][1] + b1;
                p0[8]        = acc[g][mt][2] + b0;
                p0[4096 + 8] = acc[g][mt][3] + b1;
            }
        }
    }
}

// ---------------- launch ----------------
extern "C" void kernel_launch(void* const* d_in, const int* in_sizes, int n_in,
                              void* d_out, int out_size) {
    const float* x      = (const float*)d_in[0];  // (4,256,64,64)
    const float* weight = (const float*)d_in[1];  // (256,256,3,3)
    const float* bias   = (const float*)d_in[2];  // (256,)
    const float* off_w  = (const float*)d_in[3];  // (18,256,3,3)
    const float* off_b  = (const float*)d_in[4];  // (18,)
    const float* mask_w = (const float*)d_in[5];  // (9,256,3,3)
    const float* mask_b = (const float*)d_in[6];  // (9,)
    float* out = (float*)d_out;                   // (4,256,64,64)

    cudaFuncSetAttribute(k_main, cudaFuncAttributeMaxDynamicSharedMemorySize, SMEM_TOTAL);

    prep_kernel<<<(COUT * KTOT + 255) / 256, 256>>>(weight, off_w, mask_w);
    k_offmask<<<BB * 64, 256>>>(x, off_b, mask_b);
    k_main<<<BB * 32, 512, SMEM_TOTAL>>>(x, bias, out);
}